// round 8
// baseline (speedup 1.0000x reference)
#include <cuda_runtime.h>
#include <math.h>
#include <stdint.h>

// Problem constants
#define T_LEN 2048
#define C_DIM 1024
#define H_NUM 16
#define KVH_NUM 4
#define D_DIM 64
#define KV_DIM 256
#define LOG2E 1.4426950408889634f
#define SCALE2 (0.125f * LOG2E)
#define NEG_BIG -1e30f

// Scratch
__device__ float g_q[T_LEN * C_DIM];
__device__ float g_k[T_LEN * KV_DIM];
__device__ float g_v[T_LEN * KV_DIM];
__device__ float g_y[T_LEN * C_DIM];
__device__ float g_logf[H_NUM * T_LEN];
__device__ float g_c[H_NUM * T_LEN];
__device__ float g_po[2 * T_LEN * C_DIM];
__device__ float2 g_pml[2 * H_NUM * T_LEN];

// ---------------------------------------------------------------------------
// helpers
// ---------------------------------------------------------------------------
__device__ __forceinline__ uint32_t tf32r(float x) {
    uint32_t u;
    asm("cvt.rna.tf32.f32 %0, %1;" : "=r"(u) : "f"(x));
    return u;
}
__device__ __forceinline__ float4 tf32r4(float4 v) {
    return make_float4(__uint_as_float(tf32r(v.x)), __uint_as_float(tf32r(v.y)),
                       __uint_as_float(tf32r(v.z)), __uint_as_float(tf32r(v.w)));
}
__device__ __forceinline__ float fex2(float x) {
    float r;
    asm("ex2.approx.ftz.f32 %0, %1;" : "=f"(r) : "f"(x));
    return r;
}
__device__ __forceinline__ void mma_tf32(float* c, const uint32_t* a,
                                         uint32_t b0, uint32_t b1) {
    asm volatile(
        "mma.sync.aligned.m16n8k8.row.col.f32.tf32.tf32.f32 "
        "{%0,%1,%2,%3}, {%4,%5,%6,%7}, {%8,%9}, {%0,%1,%2,%3};"
        : "+f"(c[0]), "+f"(c[1]), "+f"(c[2]), "+f"(c[3])
        : "r"(a[0]), "r"(a[1]), "r"(a[2]), "r"(a[3]), "r"(b0), "r"(b1));
}
__device__ __forceinline__ void mma_tf32f(float* c, const uint32_t* a,
                                          float b0, float b1) {
    mma_tf32(c, a, __float_as_uint(b0), __float_as_uint(b1));
}

// ---------------------------------------------------------------------------
// GEMM: O[M,N] = A[M,K] @ W[N,K]^T (unchanged)
// ---------------------------------------------------------------------------
#define GSTR 20
__global__ __launch_bounds__(256, 2)
void gemm_tf32_kernel(const float* __restrict__ A,
                      const float* __restrict__ Wq, float* __restrict__ Oq,
                      const float* __restrict__ Wk, float* __restrict__ Ok,
                      const float* __restrict__ Wv, float* __restrict__ Ov,
                      int K, int fused) {
    __shared__ float As[2][128][GSTR];
    __shared__ float Ws[2][64][GSTR];

    const int bx = blockIdx.x;
    const float* W;
    float* O;
    int n0, Nout;
    if (fused && bx >= 16) {
        if (bx < 20) { W = Wk; O = Ok; n0 = (bx - 16) << 6; }
        else         { W = Wv; O = Ov; n0 = (bx - 20) << 6; }
        Nout = KV_DIM;
    } else {
        W = Wq; O = Oq; n0 = bx << 6; Nout = C_DIM;
    }
    const int m0 = blockIdx.y << 7;
    const int tid = threadIdx.x, wid = tid >> 5, lane = tid & 31;
    const int grp = lane >> 2, tg = lane & 3;
    const int wm = (wid & 3) << 5, wn = (wid >> 2) << 5;
    const int ar = tid >> 2, ac = (tid & 3) << 2;

    const float* Abase = A + (size_t)(m0 + ar) * K + ac;
    const float* Wbase = W + (size_t)(n0 + ar) * K + ac;

    float acc[2][4][4] = {};

    {
        float4 a0 = *(const float4*)(Abase);
        float4 a1 = *(const float4*)(Abase + (size_t)64 * K);
        float4 w0 = *(const float4*)(Wbase);
        *(float4*)&As[0][ar][ac] = tf32r4(a0);
        *(float4*)&As[0][ar + 64][ac] = tf32r4(a1);
        *(float4*)&Ws[0][ar][ac] = tf32r4(w0);
    }
    __syncthreads();

    const int NK = K >> 4;
#pragma unroll 2
    for (int ks = 0; ks < NK; ks++) {
        const int s = ks & 1;
        float4 a0, a1, w0;
        const bool has = (ks + 1 < NK);
        if (has) {
            const float* ap = Abase + (ks + 1) * 16;
            const float* wp = Wbase + (ks + 1) * 16;
            a0 = *(const float4*)(ap);
            a1 = *(const float4*)(ap + (size_t)64 * K);
            w0 = *(const float4*)(wp);
        }
#pragma unroll
        for (int kb = 0; kb < 16; kb += 8) {
            uint32_t af[2][4];
#pragma unroll
            for (int mt = 0; mt < 2; mt++) {
                int mr = wm + (mt << 4);
                af[mt][0] = __float_as_uint(As[s][mr + grp][kb + tg]);
                af[mt][1] = __float_as_uint(As[s][mr + 8 + grp][kb + tg]);
                af[mt][2] = __float_as_uint(As[s][mr + grp][kb + tg + 4]);
                af[mt][3] = __float_as_uint(As[s][mr + 8 + grp][kb + tg + 4]);
            }
#pragma unroll
            for (int nt = 0; nt < 4; nt++) {
                int nc = wn + (nt << 3);
                uint32_t b0 = __float_as_uint(Ws[s][nc + grp][kb + tg]);
                uint32_t b1 = __float_as_uint(Ws[s][nc + grp][kb + tg + 4]);
                mma_tf32(acc[0][nt], af[0], b0, b1);
                mma_tf32(acc[1][nt], af[1], b0, b1);
            }
        }
        if (has) {
            *(float4*)&As[s ^ 1][ar][ac] = tf32r4(a0);
            *(float4*)&As[s ^ 1][ar + 64][ac] = tf32r4(a1);
            *(float4*)&Ws[s ^ 1][ar][ac] = tf32r4(w0);
        }
        __syncthreads();
    }
#pragma unroll
    for (int mt = 0; mt < 2; mt++)
#pragma unroll
        for (int nt = 0; nt < 4; nt++) {
            int row = m0 + wm + (mt << 4) + grp;
            int col = n0 + wn + (nt << 3) + (tg << 1);
            *(float2*)&O[(size_t)row * Nout + col] =
                make_float2(acc[mt][nt][0], acc[mt][nt][1]);
            *(float2*)&O[(size_t)(row + 8) * Nout + col] =
                make_float2(acc[mt][nt][2], acc[mt][nt][3]);
        }
}

// ---------------------------------------------------------------------------
// RMSNorm + RoPE + (blocks 0..15) per-head cumsum (unchanged).
// ---------------------------------------------------------------------------
__global__ void normrope_kernel(float* __restrict__ q, float* __restrict__ k,
                                const float* __restrict__ qw,
                                const float* __restrict__ kw,
                                const float* __restrict__ lf,
                                float* __restrict__ cgout) {
    const int t = blockIdx.x;
    const int tid = threadIdx.x;
    __shared__ float buf[C_DIM];
    __shared__ float cs[32], sn[32];
    __shared__ float red[8];
    __shared__ float s_inv;

    if (tid < 32) {
        float th = (float)t * fex2((float)tid * -0.41524101186092029f);
        cs[tid] = cosf(th);
        sn[tid] = sinf(th);
    }

    float ss = 0.f;
    for (int c = tid; c < C_DIM; c += 256) {
        float vv = q[(size_t)t * C_DIM + c];
        buf[c] = vv;
        ss += vv * vv;
    }
#pragma unroll
    for (int o = 16; o; o >>= 1) ss += __shfl_xor_sync(0xffffffffu, ss, o);
    if ((tid & 31) == 0) red[tid >> 5] = ss;
    __syncthreads();
    if (tid == 0) {
        float tot = 0.f;
#pragma unroll
        for (int w = 0; w < 8; w++) tot += red[w];
        s_inv = rsqrtf(tot / (float)C_DIM + 1e-6f);
    }
    __syncthreads();
    float inv = s_inv;
    for (int c = tid; c < C_DIM; c += 256) {
        int d = c & 63;
        int f = d & 31;
        float xn = buf[c] * inv * qw[c];
        float other = (d < 32) ? -buf[c + 32] * inv * qw[c + 32]
                               :  buf[c - 32] * inv * qw[c - 32];
        q[(size_t)t * C_DIM + c] = xn * cs[f] + other * sn[f];
    }
    __syncthreads();

    float ss2 = 0.f;
    if (tid < KV_DIM) {
        float vv = k[(size_t)t * KV_DIM + tid];
        buf[tid] = vv;
        ss2 = vv * vv;
    }
#pragma unroll
    for (int o = 16; o; o >>= 1) ss2 += __shfl_xor_sync(0xffffffffu, ss2, o);
    if ((tid & 31) == 0) red[tid >> 5] = ss2;
    __syncthreads();
    if (tid == 0) {
        float tot = 0.f;
#pragma unroll
        for (int w = 0; w < 8; w++) tot += red[w];
        s_inv = rsqrtf(tot / (float)KV_DIM + 1e-6f);
    }
    __syncthreads();
    inv = s_inv;
    if (tid < KV_DIM) {
        int c = tid;
        int d = c & 63;
        int f = d & 31;
        float xn = buf[c] * inv * kw[c];
        float other = (d < 32) ? -buf[c + 32] * inv * kw[c + 32]
                               :  buf[c - 32] * inv * kw[c - 32];
        k[(size_t)t * KV_DIM + c] = xn * cs[f] + other * sn[f];
    }

    if (blockIdx.x < 16 && tid < 32) {
        const int h = blockIdx.x;
        const int lane = tid;
        const float* src = lf + (size_t)h * T_LEN;
        float* dst = cgout + (size_t)h * T_LEN;
        const int base = lane * 64;
        float s = 0.f;
#pragma unroll 8
        for (int i = 0; i < 64; i++) s += src[base + i];
        float incl = s;
#pragma unroll
        for (int o = 1; o < 32; o <<= 1) {
            float vv = __shfl_up_sync(0xffffffffu, incl, o);
            if (lane >= o) incl += vv;
        }
        float run = incl - s;
#pragma unroll 8
        for (int i = 0; i < 64; i++) {
            run += src[base + i];
            dst[base + i] = run * LOG2E;
        }
    }
}

// ---------------------------------------------------------------------------
// Forgetting gate (unchanged).
// ---------------------------------------------------------------------------
__global__ __launch_bounds__(256, 2)
void gate_kernel(const float* __restrict__ x,
                 const float* __restrict__ wl,
                 const float* __restrict__ fg,
                 const float* __restrict__ fb,
                 float* __restrict__ logf_out) {
    __shared__ float xs[8][C_DIM];
    const int t0 = blockIdx.x << 3;
    const int tid = threadIdx.x;
    for (int i = tid; i < 8 * C_DIM; i += 256)
        xs[i >> 10][i & 1023] = x[(size_t)t0 * C_DIM + i];
    __syncthreads();

    const int h = tid >> 4, l16 = tid & 15;
    float z1[8] = {}, z2[8] = {};
    for (int c = l16; c < C_DIM; c += 16) {
        float wlv = wl[(size_t)c * H_NUM + h];
        float fgv = fg[(size_t)h * C_DIM + c];
#pragma unroll
        for (int g = 0; g < 8; g++) {
            float xv = xs[g][c];
            z1[g] += xv * wlv;
            z2[g] += xv * fgv;
        }
    }
#pragma unroll
    for (int o = 8; o; o >>= 1) {
#pragma unroll
        for (int g = 0; g < 8; g++) {
            z1[g] += __shfl_xor_sync(0xffffffffu, z1[g], o);
            z2[g] += __shfl_xor_sync(0xffffffffu, z2[g], o);
        }
    }
    if (l16 == 0) {
        float fbv = fb[h];
#pragma unroll
        for (int g = 0; g < 8; g++) {
            float lam = (z1[g] > 0.f ? z1[g] : expf(z1[g]) - 1.f) + 1.f;
            float logit = (z2[g] + fbv) * lam;
            float ls = (logit >= 0.f) ? -log1pf(expf(-logit))
                                      : (logit - log1pf(expf(logit)));
            logf_out[(size_t)h * T_LEN + t0 + g] = ls / (lam + 1e-3f);
        }
    }
}

// ---------------------------------------------------------------------------
// Flash attention SPLIT-K partials with fragment-permuted smem.
// K layout: row-major 72-stride, column c at (c&3)*16 + (c>>2)
//   -> lane tg reads its 16 (b0,b1) values for all kt as 4x LDS.128.
// V layout: row-major 72-stride, column d at (d&7)*8 + (d>>3)
//   -> lane reads 8 nt-values per row as 2x LDS.128.
// ---------------------------------------------------------------------------
#define KRS 72
__global__ __launch_bounds__(256, 2)
void attn_part_kernel(const float* __restrict__ q, const float* __restrict__ k,
                      const float* __restrict__ v, const float* __restrict__ cg,
                      float* __restrict__ po, float2* __restrict__ pml) {
    __shared__ float Ks[64 * KRS];
    __shared__ float Vs[64 * KRS];
    __shared__ float cjs[4][64];

    const int kvh = blockIdx.y >> 1;
    const int seg = blockIdx.y & 1;
    const int qt = 63 - blockIdx.x;
    const int i0 = qt << 5;
    const int tid = threadIdx.x, wid = tid >> 5, lane = tid & 31;
    const int grp = lane >> 2, tg = lane & 3;
    const int hl = wid >> 1;
    const int qh = (kvh << 2) + hl;
    const int r0 = i0 + ((wid & 1) << 4) + grp;
    const int r1 = r0 + 8;

    const int ntiles = ((i0 + 31) >> 6) + 1;
    const int half = (ntiles + 1) >> 1;
    const int tb = seg ? half : 0;
    const int te = seg ? ntiles : half;

    float* poseg = po + (size_t)seg * T_LEN * C_DIM;
    float2* pmlseg = pml + (size_t)seg * H_NUM * T_LEN;

    if (tb >= te) {
        if (tid < 128) {
            int hh = tid >> 5, tt = i0 + (tid & 31);
            pmlseg[(size_t)((kvh << 2) + hh) * T_LEN + tt] =
                make_float2(NEG_BIG, 0.f);
        }
        return;
    }

    uint32_t qa[8][4];
#pragma unroll
    for (int kt = 0; kt < 8; kt++) {
        const float* q0 = q + (size_t)r0 * C_DIM + qh * 64 + (kt << 3);
        const float* q1 = q + (size_t)r1 * C_DIM + qh * 64 + (kt << 3);
        qa[kt][0] = tf32r(q0[tg]);
        qa[kt][1] = tf32r(q1[tg]);
        qa[kt][2] = tf32r(q0[tg + 4]);
        qa[kt][3] = tf32r(q1[tg + 4]);
    }
    const float ci0 = cg[qh * T_LEN + r0], ci1 = cg[qh * T_LEN + r1];

    float m0 = NEG_BIG, m1 = NEG_BIG, l0 = 0.f, l1 = 0.f;
    float o[8][4] = {};

    for (int jt = tb; jt < te; jt++) {
        const int j0 = jt << 6;
        __syncthreads();
        // load K,V tiles into fragment-permuted smem
#pragma unroll
        for (int t = 0; t < 4; t++) {
            int idx = tid + (t << 8);
            int r = idx >> 4, c4 = (idx & 15) << 2;
            float4 kk = tf32r4(*(const float4*)(
                k + (size_t)(j0 + r) * KV_DIM + kvh * 64 + c4));
            float* kb = Ks + r * KRS + (c4 >> 2);
            kb[0] = kk.x; kb[16] = kk.y; kb[32] = kk.z; kb[48] = kk.w;
            float4 vv = tf32r4(*(const float4*)(
                v + (size_t)(j0 + r) * KV_DIM + kvh * 64 + c4));
            float* vb = Vs + r * KRS + ((c4 & 7) << 3) + (c4 >> 3);
            vb[0] = vv.x; vb[8] = vv.y; vb[16] = vv.z; vb[24] = vv.w;
        }
        cjs[tid >> 6][tid & 63] =
            cg[(size_t)((kvh << 2) + (tid >> 6)) * T_LEN + j0 + (tid & 63)];
        __syncthreads();

        // S = Q K^T  (vector B loads: 4x LDS.128 per nt-row)
        float s[8][4] = {};
#pragma unroll
        for (int nt = 0; nt < 8; nt++) {
            const float* kr = Ks + ((nt << 3) + grp) * KRS + (tg << 4);
            float4 f0 = *(const float4*)(kr);
            float4 f1 = *(const float4*)(kr + 4);
            mma_tf32f(s[nt], qa[0], f0.x, f0.y);
            mma_tf32f(s[nt], qa[1], f0.z, f0.w);
            mma_tf32f(s[nt], qa[2], f1.x, f1.y);
            mma_tf32f(s[nt], qa[3], f1.z, f1.w);
            float4 f2 = *(const float4*)(kr + 8);
            float4 f3 = *(const float4*)(kr + 12);
            mma_tf32f(s[nt], qa[4], f2.x, f2.y);
            mma_tf32f(s[nt], qa[5], f2.z, f2.w);
            mma_tf32f(s[nt], qa[6], f3.x, f3.y);
            mma_tf32f(s[nt], qa[7], f3.z, f3.w);
        }

        const bool diag = (jt == ntiles - 1);
        float mt0 = NEG_BIG, mt1 = NEG_BIG;
#pragma unroll
        for (int nt = 0; nt < 8; nt++) {
            int c0 = (nt << 3) + (tg << 1), c1 = c0 + 1;
            float b0v = cjs[hl][c0], b1v = cjs[hl][c1];
            s[nt][0] = s[nt][0] * SCALE2 + ci0 - b0v;
            s[nt][1] = s[nt][1] * SCALE2 + ci0 - b1v;
            s[nt][2] = s[nt][2] * SCALE2 + ci1 - b0v;
            s[nt][3] = s[nt][3] * SCALE2 + ci1 - b1v;
            if (diag) {
                if (j0 + c0 > r0) s[nt][0] = NEG_BIG;
                if (j0 + c1 > r0) s[nt][1] = NEG_BIG;
                if (j0 + c0 > r1) s[nt][2] = NEG_BIG;
                if (j0 + c1 > r1) s[nt][3] = NEG_BIG;
            }
            mt0 = fmaxf(mt0, fmaxf(s[nt][0], s[nt][1]));
            mt1 = fmaxf(mt1, fmaxf(s[nt][2], s[nt][3]));
        }
        mt0 = fmaxf(mt0, __shfl_xor_sync(0xffffffffu, mt0, 1));
        mt0 = fmaxf(mt0, __shfl_xor_sync(0xffffffffu, mt0, 2));
        mt1 = fmaxf(mt1, __shfl_xor_sync(0xffffffffu, mt1, 1));
        mt1 = fmaxf(mt1, __shfl_xor_sync(0xffffffffu, mt1, 2));

        float mn0 = fmaxf(m0, mt0), mn1 = fmaxf(m1, mt1);
        float al0 = fex2(m0 - mn0), al1 = fex2(m1 - mn1);
        float ps0 = 0.f, ps1 = 0.f;
#pragma unroll
        for (int nt = 0; nt < 8; nt++) {
            s[nt][0] = fex2(s[nt][0] - mn0);
            s[nt][1] = fex2(s[nt][1] - mn0);
            s[nt][2] = fex2(s[nt][2] - mn1);
            s[nt][3] = fex2(s[nt][3] - mn1);
            ps0 += s[nt][0] + s[nt][1];
            ps1 += s[nt][2] + s[nt][3];
        }
        ps0 += __shfl_xor_sync(0xffffffffu, ps0, 1);
        ps0 += __shfl_xor_sync(0xffffffffu, ps0, 2);
        ps1 += __shfl_xor_sync(0xffffffffu, ps1, 1);
        ps1 += __shfl_xor_sync(0xffffffffu, ps1, 2);
        l0 = l0 * al0 + ps0;
        l1 = l1 * al1 + ps1;
        m0 = mn0; m1 = mn1;
#pragma unroll
        for (int nt = 0; nt < 8; nt++) {
            o[nt][0] *= al0; o[nt][1] *= al0;
            o[nt][2] *= al1; o[nt][3] *= al1;
            s[nt][0] = __uint_as_float(tf32r(s[nt][0]));
            s[nt][1] = __uint_as_float(tf32r(s[nt][1]));
            s[nt][2] = __uint_as_float(tf32r(s[nt][2]));
            s[nt][3] = __uint_as_float(tf32r(s[nt][3]));
        }

        // O += P V (shuffle-built A frags + vector B loads: 4x LDS.128 per kt)
        const int srcA = (grp << 2) + (tg >> 1);
        const int srcB = srcA + 2;
        const bool odd = (tg & 1);
#pragma unroll
        for (int kt = 0; kt < 8; kt++) {
            float x0 = __shfl_sync(0xffffffffu, s[kt][0], srcA);
            float x1 = __shfl_sync(0xffffffffu, s[kt][1], srcA);
            float x2 = __shfl_sync(0xffffffffu, s[kt][2], srcA);
            float x3 = __shfl_sync(0xffffffffu, s[kt][3], srcA);
            float y0 = __shfl_sync(0xffffffffu, s[kt][0], srcB);
            float y1 = __shfl_sync(0xffffffffu, s[kt][1], srcB);
            float y2 = __shfl_sync(0xffffffffu, s[kt][2], srcB);
            float y3 = __shfl_sync(0xffffffffu, s[kt][3], srcB);
            uint32_t pa[4];
            pa[0] = __float_as_uint(odd ? x1 : x0);
            pa[1] = __float_as_uint(odd ? x3 : x2);
            pa[2] = __float_as_uint(odd ? y1 : y0);
            pa[3] = __float_as_uint(odd ? y3 : y2);

            const float* v0 = Vs + ((kt << 3) + tg) * KRS + (grp << 3);
            const float* v1 = v0 + 4 * KRS;
            float4 g0 = *(const float4*)(v0);
            float4 g1 = *(const float4*)(v0 + 4);
            float4 h0 = *(const float4*)(v1);
            float4 h1 = *(const float4*)(v1 + 4);
            mma_tf32f(o[0], pa, g0.x, h0.x);
            mma_tf32f(o[1], pa, g0.y, h0.y);
            mma_tf32f(o[2], pa, g0.z, h0.z);
            mma_tf32f(o[3], pa, g0.w, h0.w);
            mma_tf32f(o[4], pa, g1.x, h1.x);
            mma_tf32f(o[5], pa, g1.y, h1.y);
            mma_tf32f(o[6], pa, g1.z, h1.z);
            mma_tf32f(o[7], pa, g1.w, h1.w);
        }
    }

    // write unnormalized partials
#pragma unroll
    for (int nt = 0; nt < 8; nt++) {
        int col = qh * 64 + (nt << 3) + (tg << 1);
        *(float2*)&poseg[(size_t)r0 * C_DIM + col] =
            make_float2(o[nt][0], o[nt][1]);
        *(float2*)&poseg[(size_t)r1 * C_DIM + col] =
            make_float2(o[nt][2], o[nt][3]);
    }
    if (tg == 0) {
        pmlseg[(size_t)qh * T_LEN + r0] = make_float2(m0, l0);
        pmlseg[(size_t)qh * T_LEN + r1] = make_float2(m1, l1);
    }
}

// ---------------------------------------------------------------------------
// Split-K merge (unchanged)
// ---------------------------------------------------------------------------
__global__ __launch_bounds__(256)
void attn_merge_kernel(const float* __restrict__ po,
                       const float2* __restrict__ pml,
                       float* __restrict__ y) {
    const int t = blockIdx.x;
    const int c0 = threadIdx.x << 2;
    const int h = c0 >> 6;
    float2 ml0 = pml[(size_t)h * T_LEN + t];
    float2 ml1 = pml[(size_t)H_NUM * T_LEN + (size_t)h * T_LEN + t];
    float mm = fmaxf(ml0.x, ml1.x);
    float a0 = fex2(ml0.x - mm), a1 = fex2(ml1.x - mm);
    float inv = 1.f / (ml0.y * a0 + ml1.y * a1);
    float4 o0 = *(const float4*)(po + (size_t)t * C_DIM + c0);
    float4 o1 = *(const float4*)(po + (size_t)T_LEN * C_DIM + (size_t)t * C_DIM + c0);
    float4 r;
    r.x = (o0.x * a0 + o1.x * a1) * inv;
    r.y = (o0.y * a0 + o1.y * a1) * inv;
    r.z = (o0.z * a0 + o1.z * a1) * inv;
    r.w = (o0.w * a0 + o1.w * a1) * inv;
    *(float4*)(y + (size_t)t * C_DIM + c0) = r;
}

// ---------------------------------------------------------------------------
// kernel_launch — attn partial at MY launch index 3 (profiled)
// ---------------------------------------------------------------------------
extern "C" void kernel_launch(void* const* d_in, const int* in_sizes, int n_in,
                              void* d_out, int out_size) {
    const float* x  = (const float*)d_in[0];
    const float* Wq = (const float*)d_in[1];
    const float* Wk = (const float*)d_in[2];
    const float* Wv = (const float*)d_in[3];
    const float* Wo = (const float*)d_in[4];
    const float* qw = (const float*)d_in[5];
    const float* kw = (const float*)d_in[6];
    const float* fg = (const float*)d_in[7];
    const float* fb = (const float*)d_in[8];
    const float* wl = (const float*)d_in[9];
    float* out = (float*)d_out;

    float *qp, *kp, *vp, *yp, *lfp, *cp, *pop;
    float2* pmlp;
    cudaGetSymbolAddress((void**)&qp, g_q);
    cudaGetSymbolAddress((void**)&kp, g_k);
    cudaGetSymbolAddress((void**)&vp, g_v);
    cudaGetSymbolAddress((void**)&yp, g_y);
    cudaGetSymbolAddress((void**)&lfp, g_logf);
    cudaGetSymbolAddress((void**)&cp, g_c);
    cudaGetSymbolAddress((void**)&pop, g_po);
    cudaGetSymbolAddress((void**)&pmlp, g_pml);

    // 0: gate
    gate_kernel<<<T_LEN / 8, 256>>>(x, wl, fg, fb, lfp);
    // 1: fused Q/K/V projection
    gemm_tf32_kernel<<<dim3(24, T_LEN / 128), 256>>>(
        x, Wq, qp, Wk, kp, Wv, vp, C_DIM, 1);
    // 2: RMSNorm + RoPE + per-head cumsum
    normrope_kernel<<<T_LEN, 256>>>(qp, kp, qw, kw, lfp, cp);
    // 3: flash attention split-K partials (PROFILED)
    attn_part_kernel<<<dim3(64, KVH_NUM * 2), 256>>>(qp, kp, vp, cp, pop, pmlp);
    // 4: split-K merge
    attn_merge_kernel<<<T_LEN, 256>>>(pop, pmlp, yp);
    // 5: output projection
    gemm_tf32_kernel<<<dim3(16, T_LEN / 128), 256>>>(
        yp, Wo, out, Wo, out, Wo, out, C_DIM, 0);
}

// round 9
// speedup vs baseline: 1.1090x; 1.1090x over previous
#include <cuda_runtime.h>
#include <math.h>
#include <stdint.h>

// Problem constants
#define T_LEN 2048
#define C_DIM 1024
#define H_NUM 16
#define KVH_NUM 4
#define D_DIM 64
#define KV_DIM 256
#define LOG2E 1.4426950408889634f
#define SCALE2 (0.125f * LOG2E)
#define NEG_BIG -1e30f

// Scratch
__device__ float g_q[T_LEN * C_DIM];
__device__ float g_k[T_LEN * KV_DIM];
__device__ float g_v[T_LEN * KV_DIM];
__device__ float g_y[T_LEN * C_DIM];
__device__ float g_logf[H_NUM * T_LEN];
__device__ float g_c[H_NUM * T_LEN];
__device__ float g_po[2 * T_LEN * C_DIM];
__device__ float2 g_pml[2 * H_NUM * T_LEN];

// ---------------------------------------------------------------------------
// helpers
// ---------------------------------------------------------------------------
__device__ __forceinline__ uint32_t tf32r(float x) {
    uint32_t u;
    asm("cvt.rna.tf32.f32 %0, %1;" : "=r"(u) : "f"(x));
    return u;
}
__device__ __forceinline__ float4 tf32r4(float4 v) {
    return make_float4(__uint_as_float(tf32r(v.x)), __uint_as_float(tf32r(v.y)),
                       __uint_as_float(tf32r(v.z)), __uint_as_float(tf32r(v.w)));
}
__device__ __forceinline__ float fex2(float x) {
    float r;
    asm("ex2.approx.ftz.f32 %0, %1;" : "=f"(r) : "f"(x));
    return r;
}
__device__ __forceinline__ void mma_tf32(float* c, const uint32_t* a,
                                         uint32_t b0, uint32_t b1) {
    asm volatile(
        "mma.sync.aligned.m16n8k8.row.col.f32.tf32.tf32.f32 "
        "{%0,%1,%2,%3}, {%4,%5,%6,%7}, {%8,%9}, {%0,%1,%2,%3};"
        : "+f"(c[0]), "+f"(c[1]), "+f"(c[2]), "+f"(c[3])
        : "r"(a[0]), "r"(a[1]), "r"(a[2]), "r"(a[3]), "r"(b0), "r"(b1));
}
__device__ __forceinline__ void cp16(uint32_t dst, const void* src) {
    asm volatile("cp.async.cg.shared.global [%0], [%1], 16;"
                 :: "r"(dst), "l"(src));
}
__device__ __forceinline__ void cp4(uint32_t dst, const void* src) {
    asm volatile("cp.async.ca.shared.global [%0], [%1], 4;"
                 :: "r"(dst), "l"(src));
}
__device__ __forceinline__ uint32_t s2u(const void* p) {
    return (uint32_t)__cvta_generic_to_shared(p);
}

// ---------------------------------------------------------------------------
// GEMM: O[M,N] = A[M,K] @ W[N,K]^T (unchanged)
// ---------------------------------------------------------------------------
#define GSTR 20
__global__ __launch_bounds__(256, 2)
void gemm_tf32_kernel(const float* __restrict__ A,
                      const float* __restrict__ Wq, float* __restrict__ Oq,
                      const float* __restrict__ Wk, float* __restrict__ Ok,
                      const float* __restrict__ Wv, float* __restrict__ Ov,
                      int K, int fused) {
    __shared__ float As[2][128][GSTR];
    __shared__ float Ws[2][64][GSTR];

    const int bx = blockIdx.x;
    const float* W;
    float* O;
    int n0, Nout;
    if (fused && bx >= 16) {
        if (bx < 20) { W = Wk; O = Ok; n0 = (bx - 16) << 6; }
        else         { W = Wv; O = Ov; n0 = (bx - 20) << 6; }
        Nout = KV_DIM;
    } else {
        W = Wq; O = Oq; n0 = bx << 6; Nout = C_DIM;
    }
    const int m0 = blockIdx.y << 7;
    const int tid = threadIdx.x, wid = tid >> 5, lane = tid & 31;
    const int grp = lane >> 2, tg = lane & 3;
    const int wm = (wid & 3) << 5, wn = (wid >> 2) << 5;
    const int ar = tid >> 2, ac = (tid & 3) << 2;

    const float* Abase = A + (size_t)(m0 + ar) * K + ac;
    const float* Wbase = W + (size_t)(n0 + ar) * K + ac;

    float acc[2][4][4] = {};

    {
        float4 a0 = *(const float4*)(Abase);
        float4 a1 = *(const float4*)(Abase + (size_t)64 * K);
        float4 w0 = *(const float4*)(Wbase);
        *(float4*)&As[0][ar][ac] = tf32r4(a0);
        *(float4*)&As[0][ar + 64][ac] = tf32r4(a1);
        *(float4*)&Ws[0][ar][ac] = tf32r4(w0);
    }
    __syncthreads();

    const int NK = K >> 4;
#pragma unroll 2
    for (int ks = 0; ks < NK; ks++) {
        const int s = ks & 1;
        float4 a0, a1, w0;
        const bool has = (ks + 1 < NK);
        if (has) {
            const float* ap = Abase + (ks + 1) * 16;
            const float* wp = Wbase + (ks + 1) * 16;
            a0 = *(const float4*)(ap);
            a1 = *(const float4*)(ap + (size_t)64 * K);
            w0 = *(const float4*)(wp);
        }
#pragma unroll
        for (int kb = 0; kb < 16; kb += 8) {
            uint32_t af[2][4];
#pragma unroll
            for (int mt = 0; mt < 2; mt++) {
                int mr = wm + (mt << 4);
                af[mt][0] = __float_as_uint(As[s][mr + grp][kb + tg]);
                af[mt][1] = __float_as_uint(As[s][mr + 8 + grp][kb + tg]);
                af[mt][2] = __float_as_uint(As[s][mr + grp][kb + tg + 4]);
                af[mt][3] = __float_as_uint(As[s][mr + 8 + grp][kb + tg + 4]);
            }
#pragma unroll
            for (int nt = 0; nt < 4; nt++) {
                int nc = wn + (nt << 3);
                uint32_t b0 = __float_as_uint(Ws[s][nc + grp][kb + tg]);
                uint32_t b1 = __float_as_uint(Ws[s][nc + grp][kb + tg + 4]);
                mma_tf32(acc[0][nt], af[0], b0, b1);
                mma_tf32(acc[1][nt], af[1], b0, b1);
            }
        }
        if (has) {
            *(float4*)&As[s ^ 1][ar][ac] = tf32r4(a0);
            *(float4*)&As[s ^ 1][ar + 64][ac] = tf32r4(a1);
            *(float4*)&Ws[s ^ 1][ar][ac] = tf32r4(w0);
        }
        __syncthreads();
    }
#pragma unroll
    for (int mt = 0; mt < 2; mt++)
#pragma unroll
        for (int nt = 0; nt < 4; nt++) {
            int row = m0 + wm + (mt << 4) + grp;
            int col = n0 + wn + (nt << 3) + (tg << 1);
            *(float2*)&O[(size_t)row * Nout + col] =
                make_float2(acc[mt][nt][0], acc[mt][nt][1]);
            *(float2*)&O[(size_t)(row + 8) * Nout + col] =
                make_float2(acc[mt][nt][2], acc[mt][nt][3]);
        }
}

// ---------------------------------------------------------------------------
// RMSNorm + RoPE (k output tf32-rounded), v tf32-rounded in place,
// blocks 0..15 also run the per-head cumsum.
// ---------------------------------------------------------------------------
__global__ void normrope_kernel(float* __restrict__ q, float* __restrict__ k,
                                float* __restrict__ v,
                                const float* __restrict__ qw,
                                const float* __restrict__ kw,
                                const float* __restrict__ lf,
                                float* __restrict__ cgout) {
    const int t = blockIdx.x;
    const int tid = threadIdx.x;
    __shared__ float buf[C_DIM];
    __shared__ float cs[32], sn[32];
    __shared__ float red[8];
    __shared__ float s_inv;

    if (tid < 32) {
        float th = (float)t * fex2((float)tid * -0.41524101186092029f);
        cs[tid] = cosf(th);
        sn[tid] = sinf(th);
    }

    float ss = 0.f;
    for (int c = tid; c < C_DIM; c += 256) {
        float vv = q[(size_t)t * C_DIM + c];
        buf[c] = vv;
        ss += vv * vv;
    }
#pragma unroll
    for (int o = 16; o; o >>= 1) ss += __shfl_xor_sync(0xffffffffu, ss, o);
    if ((tid & 31) == 0) red[tid >> 5] = ss;
    __syncthreads();
    if (tid == 0) {
        float tot = 0.f;
#pragma unroll
        for (int w = 0; w < 8; w++) tot += red[w];
        s_inv = rsqrtf(tot / (float)C_DIM + 1e-6f);
    }
    __syncthreads();
    float inv = s_inv;
    for (int c = tid; c < C_DIM; c += 256) {
        int d = c & 63;
        int f = d & 31;
        float xn = buf[c] * inv * qw[c];
        float other = (d < 32) ? -buf[c + 32] * inv * qw[c + 32]
                               :  buf[c - 32] * inv * qw[c - 32];
        q[(size_t)t * C_DIM + c] = xn * cs[f] + other * sn[f];
    }
    __syncthreads();

    float ss2 = 0.f;
    if (tid < KV_DIM) {
        float vv = k[(size_t)t * KV_DIM + tid];
        buf[tid] = vv;
        ss2 = vv * vv;
    }
#pragma unroll
    for (int o = 16; o; o >>= 1) ss2 += __shfl_xor_sync(0xffffffffu, ss2, o);
    if ((tid & 31) == 0) red[tid >> 5] = ss2;
    __syncthreads();
    if (tid == 0) {
        float tot = 0.f;
#pragma unroll
        for (int w = 0; w < 8; w++) tot += red[w];
        s_inv = rsqrtf(tot / (float)KV_DIM + 1e-6f);
    }
    __syncthreads();
    inv = s_inv;
    if (tid < KV_DIM) {
        int c = tid;
        int d = c & 63;
        int f = d & 31;
        float xn = buf[c] * inv * kw[c];
        float other = (d < 32) ? -buf[c + 32] * inv * kw[c + 32]
                               :  buf[c - 32] * inv * kw[c - 32];
        // tf32-round so attention can cp.async raw bytes
        k[(size_t)t * KV_DIM + c] =
            __uint_as_float(tf32r(xn * cs[f] + other * sn[f]));
        // v: tf32-round in place
        v[(size_t)t * KV_DIM + c] =
            __uint_as_float(tf32r(v[(size_t)t * KV_DIM + c]));
    }

    if (blockIdx.x < 16 && tid < 32) {
        const int h = blockIdx.x;
        const int lane = tid;
        const float* src = lf + (size_t)h * T_LEN;
        float* dst = cgout + (size_t)h * T_LEN;
        const int base = lane * 64;
        float s = 0.f;
#pragma unroll 8
        for (int i = 0; i < 64; i++) s += src[base + i];
        float incl = s;
#pragma unroll
        for (int o = 1; o < 32; o <<= 1) {
            float vv = __shfl_up_sync(0xffffffffu, incl, o);
            if (lane >= o) incl += vv;
        }
        float run = incl - s;
#pragma unroll 8
        for (int i = 0; i < 64; i++) {
            run += src[base + i];
            dst[base + i] = run * LOG2E;
        }
    }
}

// ---------------------------------------------------------------------------
// Forgetting gate (unchanged).
// ---------------------------------------------------------------------------
__global__ __launch_bounds__(256, 2)
void gate_kernel(const float* __restrict__ x,
                 const float* __restrict__ wl,
                 const float* __restrict__ fg,
                 const float* __restrict__ fb,
                 float* __restrict__ logf_out) {
    __shared__ float xs[8][C_DIM];
    const int t0 = blockIdx.x << 3;
    const int tid = threadIdx.x;
    for (int i = tid; i < 8 * C_DIM; i += 256)
        xs[i >> 10][i & 1023] = x[(size_t)t0 * C_DIM + i];
    __syncthreads();

    const int h = tid >> 4, l16 = tid & 15;
    float z1[8] = {}, z2[8] = {};
    for (int c = l16; c < C_DIM; c += 16) {
        float wlv = wl[(size_t)c * H_NUM + h];
        float fgv = fg[(size_t)h * C_DIM + c];
#pragma unroll
        for (int g = 0; g < 8; g++) {
            float xv = xs[g][c];
            z1[g] += xv * wlv;
            z2[g] += xv * fgv;
        }
    }
#pragma unroll
    for (int o = 8; o; o >>= 1) {
#pragma unroll
        for (int g = 0; g < 8; g++) {
            z1[g] += __shfl_xor_sync(0xffffffffu, z1[g], o);
            z2[g] += __shfl_xor_sync(0xffffffffu, z2[g], o);
        }
    }
    if (l16 == 0) {
        float fbv = fb[h];
#pragma unroll
        for (int g = 0; g < 8; g++) {
            float lam = (z1[g] > 0.f ? z1[g] : expf(z1[g]) - 1.f) + 1.f;
            float logit = (z2[g] + fbv) * lam;
            float ls = (logit >= 0.f) ? -log1pf(expf(-logit))
                                      : (logit - log1pf(expf(logit)));
            logf_out[(size_t)h * T_LEN + t0 + g] = ls / (lam + 1e-3f);
        }
    }
}

// ---------------------------------------------------------------------------
// Flash attention SPLIT-K partials, cp.async double-buffered K/V pipeline.
// R7 compute structure (known-good numerics); K/V pre-rounded to tf32 in
// global so raw-byte cp.async preserves bit-identical math.
// Dynamic smem: 2 stages x (Ks 64x68 + Vs 64x68) = 69632 B.
// ---------------------------------------------------------------------------
#define AP 68
#define STAGE_F (2 * 64 * AP)   // floats per stage (K+V)
__shared__ float cjs_s[2][4][64];

__global__ __launch_bounds__(256, 2)
void attn_part_kernel(const float* __restrict__ q, const float* __restrict__ k,
                      const float* __restrict__ v, const float* __restrict__ cg,
                      float* __restrict__ po, float2* __restrict__ pml) {
    extern __shared__ float dsm[];

    const int kvh = blockIdx.y >> 1;
    const int seg = blockIdx.y & 1;
    const int qt = 63 - blockIdx.x;
    const int i0 = qt << 5;
    const int tid = threadIdx.x, wid = tid >> 5, lane = tid & 31;
    const int grp = lane >> 2, tg = lane & 3;
    const int hl = wid >> 1;
    const int qh = (kvh << 2) + hl;
    const int r0 = i0 + ((wid & 1) << 4) + grp;
    const int r1 = r0 + 8;

    const int ntiles = ((i0 + 31) >> 6) + 1;
    const int half = (ntiles + 1) >> 1;
    const int tb = seg ? half : 0;
    const int te = seg ? ntiles : half;

    float* poseg = po + (size_t)seg * T_LEN * C_DIM;
    float2* pmlseg = pml + (size_t)seg * H_NUM * T_LEN;

    if (tb >= te) {
        if (tid < 128) {
            int hh = tid >> 5, tt = i0 + (tid & 31);
            pmlseg[(size_t)((kvh << 2) + hh) * T_LEN + tt] =
                make_float2(NEG_BIG, 0.f);
        }
        return;
    }

    // per-tile async issue: K/V 16B chunks + cjs 4B
    const int lr = tid >> 4, lc4 = (tid & 15) << 2;   // row/col for this thread
    const int ch = tid >> 6, ct = tid & 63;           // cjs head/col
    auto issue_tile = [&](int jt) {
        const int st = jt & 1;
        const int j0 = jt << 6;
        float* Ks = dsm + st * STAGE_F;
        float* Vs = Ks + 64 * AP;
#pragma unroll
        for (int t = 0; t < 4; t++) {
            int r = lr + (t << 4);
            cp16(s2u(Ks + r * AP + lc4),
                 k + (size_t)(j0 + r) * KV_DIM + kvh * 64 + lc4);
            cp16(s2u(Vs + r * AP + lc4),
                 v + (size_t)(j0 + r) * KV_DIM + kvh * 64 + lc4);
        }
        cp4(s2u(&cjs_s[st][ch][ct]),
            cg + (size_t)((kvh << 2) + ch) * T_LEN + j0 + ct);
        asm volatile("cp.async.commit_group;");
    };

    uint32_t qa[8][4];
#pragma unroll
    for (int kt = 0; kt < 8; kt++) {
        const float* q0 = q + (size_t)r0 * C_DIM + qh * 64 + (kt << 3);
        const float* q1 = q + (size_t)r1 * C_DIM + qh * 64 + (kt << 3);
        qa[kt][0] = tf32r(q0[tg]);
        qa[kt][1] = tf32r(q1[tg]);
        qa[kt][2] = tf32r(q0[tg + 4]);
        qa[kt][3] = tf32r(q1[tg + 4]);
    }
    const float ci0 = cg[qh * T_LEN + r0], ci1 = cg[qh * T_LEN + r1];

    float m0 = NEG_BIG, m1 = NEG_BIG, l0 = 0.f, l1 = 0.f;
    float o[8][4] = {};

    issue_tile(tb);   // prologue

    for (int jt = tb; jt < te; jt++) {
        const int j0 = jt << 6;
        const int st = jt & 1;
        asm volatile("cp.async.wait_group 0;");
        __syncthreads();
        if (jt + 1 < te) issue_tile(jt + 1);

        const float* Ks = dsm + st * STAGE_F;
        const float* Vs = Ks + 64 * AP;

        // S = Q K^T
        float s[8][4] = {};
#pragma unroll
        for (int kt = 0; kt < 8; kt++) {
#pragma unroll
            for (int nt = 0; nt < 8; nt++) {
                const float* kr = Ks + ((nt << 3) + grp) * AP + (kt << 3);
                uint32_t b0 = __float_as_uint(kr[tg]);
                uint32_t b1 = __float_as_uint(kr[tg + 4]);
                mma_tf32(s[nt], qa[kt], b0, b1);
            }
        }

        const bool diag = (jt == ntiles - 1);
        float mt0 = NEG_BIG, mt1 = NEG_BIG;
#pragma unroll
        for (int nt = 0; nt < 8; nt++) {
            int c0 = (nt << 3) + (tg << 1), c1 = c0 + 1;
            float b0v = cjs_s[st][hl][c0], b1v = cjs_s[st][hl][c1];
            s[nt][0] = s[nt][0] * SCALE2 + ci0 - b0v;
            s[nt][1] = s[nt][1] * SCALE2 + ci0 - b1v;
            s[nt][2] = s[nt][2] * SCALE2 + ci1 - b0v;
            s[nt][3] = s[nt][3] * SCALE2 + ci1 - b1v;
            if (diag) {
                if (j0 + c0 > r0) s[nt][0] = NEG_BIG;
                if (j0 + c1 > r0) s[nt][1] = NEG_BIG;
                if (j0 + c0 > r1) s[nt][2] = NEG_BIG;
                if (j0 + c1 > r1) s[nt][3] = NEG_BIG;
            }
            mt0 = fmaxf(mt0, fmaxf(s[nt][0], s[nt][1]));
            mt1 = fmaxf(mt1, fmaxf(s[nt][2], s[nt][3]));
        }
        mt0 = fmaxf(mt0, __shfl_xor_sync(0xffffffffu, mt0, 1));
        mt0 = fmaxf(mt0, __shfl_xor_sync(0xffffffffu, mt0, 2));
        mt1 = fmaxf(mt1, __shfl_xor_sync(0xffffffffu, mt1, 1));
        mt1 = fmaxf(mt1, __shfl_xor_sync(0xffffffffu, mt1, 2));

        float mn0 = fmaxf(m0, mt0), mn1 = fmaxf(m1, mt1);
        float al0 = fex2(m0 - mn0), al1 = fex2(m1 - mn1);
        float ps0 = 0.f, ps1 = 0.f;
#pragma unroll
        for (int nt = 0; nt < 8; nt++) {
            s[nt][0] = fex2(s[nt][0] - mn0);
            s[nt][1] = fex2(s[nt][1] - mn0);
            s[nt][2] = fex2(s[nt][2] - mn1);
            s[nt][3] = fex2(s[nt][3] - mn1);
            ps0 += s[nt][0] + s[nt][1];
            ps1 += s[nt][2] + s[nt][3];
        }
        ps0 += __shfl_xor_sync(0xffffffffu, ps0, 1);
        ps0 += __shfl_xor_sync(0xffffffffu, ps0, 2);
        ps1 += __shfl_xor_sync(0xffffffffu, ps1, 1);
        ps1 += __shfl_xor_sync(0xffffffffu, ps1, 2);
        l0 = l0 * al0 + ps0;
        l1 = l1 * al1 + ps1;
        m0 = mn0; m1 = mn1;
#pragma unroll
        for (int nt = 0; nt < 8; nt++) {
            o[nt][0] *= al0; o[nt][1] *= al0;
            o[nt][2] *= al1; o[nt][3] *= al1;
            s[nt][0] = __uint_as_float(tf32r(s[nt][0]));
            s[nt][1] = __uint_as_float(tf32r(s[nt][1]));
            s[nt][2] = __uint_as_float(tf32r(s[nt][2]));
            s[nt][3] = __uint_as_float(tf32r(s[nt][3]));
        }

        // O += P V (shuffle-built A frags)
        const int srcA = (grp << 2) + (tg >> 1);
        const int srcB = srcA + 2;
        const bool odd = (tg & 1);
#pragma unroll
        for (int kt = 0; kt < 8; kt++) {
            float x0 = __shfl_sync(0xffffffffu, s[kt][0], srcA);
            float x1 = __shfl_sync(0xffffffffu, s[kt][1], srcA);
            float x2 = __shfl_sync(0xffffffffu, s[kt][2], srcA);
            float x3 = __shfl_sync(0xffffffffu, s[kt][3], srcA);
            float y0 = __shfl_sync(0xffffffffu, s[kt][0], srcB);
            float y1 = __shfl_sync(0xffffffffu, s[kt][1], srcB);
            float y2 = __shfl_sync(0xffffffffu, s[kt][2], srcB);
            float y3 = __shfl_sync(0xffffffffu, s[kt][3], srcB);
            uint32_t pa[4];
            pa[0] = __float_as_uint(odd ? x1 : x0);
            pa[1] = __float_as_uint(odd ? x3 : x2);
            pa[2] = __float_as_uint(odd ? y1 : y0);
            pa[3] = __float_as_uint(odd ? y3 : y2);
#pragma unroll
            for (int nt = 0; nt < 8; nt++) {
                const float* vr = Vs + ((kt << 3) + tg) * AP + (nt << 3) + grp;
                uint32_t b0 = __float_as_uint(vr[0]);
                uint32_t b1 = __float_as_uint(vr[4 * AP]);
                mma_tf32(o[nt], pa, b0, b1);
            }
        }
    }

    // write unnormalized partials
#pragma unroll
    for (int nt = 0; nt < 8; nt++) {
        int col = qh * 64 + (nt << 3) + (tg << 1);
        *(float2*)&poseg[(size_t)r0 * C_DIM + col] =
            make_float2(o[nt][0], o[nt][1]);
        *(float2*)&poseg[(size_t)r1 * C_DIM + col] =
            make_float2(o[nt][2], o[nt][3]);
    }
    if (tg == 0) {
        pmlseg[(size_t)qh * T_LEN + r0] = make_float2(m0, l0);
        pmlseg[(size_t)qh * T_LEN + r1] = make_float2(m1, l1);
    }
}

// ---------------------------------------------------------------------------
// Split-K merge (unchanged)
// ---------------------------------------------------------------------------
__global__ __launch_bounds__(256)
void attn_merge_kernel(const float* __restrict__ po,
                       const float2* __restrict__ pml,
                       float* __restrict__ y) {
    const int t = blockIdx.x;
    const int c0 = threadIdx.x << 2;
    const int h = c0 >> 6;
    float2 ml0 = pml[(size_t)h * T_LEN + t];
    float2 ml1 = pml[(size_t)H_NUM * T_LEN + (size_t)h * T_LEN + t];
    float mm = fmaxf(ml0.x, ml1.x);
    float a0 = fex2(ml0.x - mm), a1 = fex2(ml1.x - mm);
    float inv = 1.f / (ml0.y * a0 + ml1.y * a1);
    float4 o0 = *(const float4*)(po + (size_t)t * C_DIM + c0);
    float4 o1 = *(const float4*)(po + (size_t)T_LEN * C_DIM + (size_t)t * C_DIM + c0);
    float4 r;
    r.x = (o0.x * a0 + o1.x * a1) * inv;
    r.y = (o0.y * a0 + o1.y * a1) * inv;
    r.z = (o0.z * a0 + o1.z * a1) * inv;
    r.w = (o0.w * a0 + o1.w * a1) * inv;
    *(float4*)(y + (size_t)t * C_DIM + c0) = r;
}

// ---------------------------------------------------------------------------
// kernel_launch — attn partial at MY launch index 3 (profiled)
// ---------------------------------------------------------------------------
extern "C" void kernel_launch(void* const* d_in, const int* in_sizes, int n_in,
                              void* d_out, int out_size) {
    const float* x  = (const float*)d_in[0];
    const float* Wq = (const float*)d_in[1];
    const float* Wk = (const float*)d_in[2];
    const float* Wv = (const float*)d_in[3];
    const float* Wo = (const float*)d_in[4];
    const float* qw = (const float*)d_in[5];
    const float* kw = (const float*)d_in[6];
    const float* fg = (const float*)d_in[7];
    const float* fb = (const float*)d_in[8];
    const float* wl = (const float*)d_in[9];
    float* out = (float*)d_out;

    float *qp, *kp, *vp, *yp, *lfp, *cp, *pop;
    float2* pmlp;
    cudaGetSymbolAddress((void**)&qp, g_q);
    cudaGetSymbolAddress((void**)&kp, g_k);
    cudaGetSymbolAddress((void**)&vp, g_v);
    cudaGetSymbolAddress((void**)&yp, g_y);
    cudaGetSymbolAddress((void**)&lfp, g_logf);
    cudaGetSymbolAddress((void**)&cp, g_c);
    cudaGetSymbolAddress((void**)&pop, g_po);
    cudaGetSymbolAddress((void**)&pmlp, g_pml);

    const int attn_smem = 2 * STAGE_F * (int)sizeof(float);   // 69632 B
    cudaFuncSetAttribute(attn_part_kernel,
                         cudaFuncAttributeMaxDynamicSharedMemorySize, attn_smem);

    // 0: gate
    gate_kernel<<<T_LEN / 8, 256>>>(x, wl, fg, fb, lfp);
    // 1: fused Q/K/V projection
    gemm_tf32_kernel<<<dim3(24, T_LEN / 128), 256>>>(
        x, Wq, qp, Wk, kp, Wv, vp, C_DIM, 1);
    // 2: RMSNorm + RoPE (+ k/v tf32 rounding) + per-head cumsum
    normrope_kernel<<<T_LEN, 256>>>(qp, kp, vp, qw, kw, lfp, cp);
    // 3: flash attention split-K partials (PROFILED)
    attn_part_kernel<<<dim3(64, KVH_NUM * 2), 256, attn_smem>>>(
        qp, kp, vp, cp, pop, pmlp);
    // 4: split-K merge
    attn_merge_kernel<<<T_LEN, 256>>>(pop, pmlp, yp);
    // 5: output projection
    gemm_tf32_kernel<<<dim3(16, T_LEN / 128), 256>>>(
        yp, Wo, out, Wo, out, Wo, out, C_DIM, 0);
}